// round 8
// baseline (speedup 1.0000x reference)
#include <cuda_runtime.h>
#include <cuda_bf16.h>
#include <math_constants.h>

// Problem constants
#define BATCH 8
#define HH 56
#define WW 56
#define CC 256
#define NPIX (BATCH*HH*WW)        // 25088
#define NH 8
#define HD 32
#define NWIN 7
#define NREG 49
#define RS 8                      // region side
#define S_TOK 64                  // tokens per region
#define TOPK 4
#define TS 256                    // TOPK * S_TOK
#define K2 32                     // token top-k

#define FULLMASK 0xffffffffu

// ------------------------- scratch (device globals; no allocation) -----------
__device__ float g_qkv[NPIX * 768];     // (pixel, 768) : q | k | v  (~77MB)
__device__ float g_ao [NPIX * CC];      // attention out (+lepe), NHWC (~26MB)
__device__ float g_qr [BATCH * NREG * CC];
__device__ float g_kr [BATCH * NREG * CC];
__device__ int   g_idx[BATCH * NREG * TOPK];

// ------------------------- generic fp32 GEMM:  C = A * W^T + bias ------------
// A: [M x K] row-major, leading dim lda. W: [N x K] row-major. C: [M x ldc].
// Tile 128x128x16, 256 threads, 8x8 per thread (two 4-col halves, conflict-free
// LDS), register-prefetch double buffer.
#define BM 128
#define BN 128
#define BK 16

__global__ __launch_bounds__(256)
void gemm_bias_kernel(const float* __restrict__ A, int lda,
                      const float* __restrict__ W,
                      const float* __restrict__ bias,
                      float* __restrict__ C, int ldc,
                      int K)
{
    __shared__ float As[2][BK][BM + 4];
    __shared__ float Bs[2][BK][BN + 4];

    const int tid  = threadIdx.x;
    const int row0 = blockIdx.y * BM;
    const int col0 = blockIdx.x * BN;
    const int tx = tid & 15;          // 0..15 -> cols tx*4 and 64+tx*4
    const int ty = tid >> 4;          // 0..15 -> 8 rows each

    const int la_r0 = (tid * 2)     >> 2, la_c0 = (tid * 2)     & 3;
    const int la_r1 = (tid * 2 + 1) >> 2, la_c1 = (tid * 2 + 1) & 3;

    float acc[8][8];                  // [r][0..3] -> cols tx*4.. ; [r][4..7] -> 64+tx*4..
#pragma unroll
    for (int r = 0; r < 8; r++)
#pragma unroll
        for (int c = 0; c < 8; c++) acc[r][c] = 0.f;

    float4 pa0 = *(const float4*)&A[(long)(row0 + la_r0) * lda + la_c0 * 4];
    float4 pa1 = *(const float4*)&A[(long)(row0 + la_r1) * lda + la_c1 * 4];
    float4 pb0 = *(const float4*)&W[(long)(col0 + la_r0) * K   + la_c0 * 4];
    float4 pb1 = *(const float4*)&W[(long)(col0 + la_r1) * K   + la_c1 * 4];

    int buf = 0;
    {
        As[0][la_c0*4+0][la_r0] = pa0.x; As[0][la_c0*4+1][la_r0] = pa0.y;
        As[0][la_c0*4+2][la_r0] = pa0.z; As[0][la_c0*4+3][la_r0] = pa0.w;
        As[0][la_c1*4+0][la_r1] = pa1.x; As[0][la_c1*4+1][la_r1] = pa1.y;
        As[0][la_c1*4+2][la_r1] = pa1.z; As[0][la_c1*4+3][la_r1] = pa1.w;
        Bs[0][la_c0*4+0][la_r0] = pb0.x; Bs[0][la_c0*4+1][la_r0] = pb0.y;
        Bs[0][la_c0*4+2][la_r0] = pb0.z; Bs[0][la_c0*4+3][la_r0] = pb0.w;
        Bs[0][la_c1*4+0][la_r1] = pb1.x; Bs[0][la_c1*4+1][la_r1] = pb1.y;
        Bs[0][la_c1*4+2][la_r1] = pb1.z; Bs[0][la_c1*4+3][la_r1] = pb1.w;
    }
    __syncthreads();

    for (int k0 = 0; k0 < K; k0 += BK) {
        if (k0 + BK < K) {
            int kn = k0 + BK;
            pa0 = *(const float4*)&A[(long)(row0 + la_r0) * lda + kn + la_c0 * 4];
            pa1 = *(const float4*)&A[(long)(row0 + la_r1) * lda + kn + la_c1 * 4];
            pb0 = *(const float4*)&W[(long)(col0 + la_r0) * K   + kn + la_c0 * 4];
            pb1 = *(const float4*)&W[(long)(col0 + la_r1) * K   + kn + la_c1 * 4];
        }
#pragma unroll
        for (int kk = 0; kk < BK; kk++) {
            float4 a0 = *(const float4*)&As[buf][kk][ty * 8];
            float4 a1 = *(const float4*)&As[buf][kk][ty * 8 + 4];
            float4 b0 = *(const float4*)&Bs[buf][kk][tx * 4];        // conflict-free
            float4 b1 = *(const float4*)&Bs[buf][kk][64 + tx * 4];   // conflict-free
            float ar[8] = {a0.x,a0.y,a0.z,a0.w,a1.x,a1.y,a1.z,a1.w};
            float br[8] = {b0.x,b0.y,b0.z,b0.w,b1.x,b1.y,b1.z,b1.w};
#pragma unroll
            for (int r = 0; r < 8; r++)
#pragma unroll
                for (int c = 0; c < 8; c++)
                    acc[r][c] += ar[r] * br[c];
        }
        if (k0 + BK < K) {
            int nb = buf ^ 1;
            As[nb][la_c0*4+0][la_r0] = pa0.x; As[nb][la_c0*4+1][la_r0] = pa0.y;
            As[nb][la_c0*4+2][la_r0] = pa0.z; As[nb][la_c0*4+3][la_r0] = pa0.w;
            As[nb][la_c1*4+0][la_r1] = pa1.x; As[nb][la_c1*4+1][la_r1] = pa1.y;
            As[nb][la_c1*4+2][la_r1] = pa1.z; As[nb][la_c1*4+3][la_r1] = pa1.w;
            Bs[nb][la_c0*4+0][la_r0] = pb0.x; Bs[nb][la_c0*4+1][la_r0] = pb0.y;
            Bs[nb][la_c0*4+2][la_r0] = pb0.z; Bs[nb][la_c0*4+3][la_r0] = pb0.w;
            Bs[nb][la_c1*4+0][la_r1] = pb1.x; Bs[nb][la_c1*4+1][la_r1] = pb1.y;
            Bs[nb][la_c1*4+2][la_r1] = pb1.z; Bs[nb][la_c1*4+3][la_r1] = pb1.w;
            __syncthreads();
            buf = nb;
        }
    }

    float4 bb0 = *(const float4*)&bias[col0 + tx * 4];
    float4 bb1 = *(const float4*)&bias[col0 + 64 + tx * 4];
    float bcol[8] = {bb0.x,bb0.y,bb0.z,bb0.w,bb1.x,bb1.y,bb1.z,bb1.w};
#pragma unroll
    for (int r = 0; r < 8; r++) {
        float4 o0, o1;
        o0.x = acc[r][0] + bcol[0]; o0.y = acc[r][1] + bcol[1];
        o0.z = acc[r][2] + bcol[2]; o0.w = acc[r][3] + bcol[3];
        o1.x = acc[r][4] + bcol[4]; o1.y = acc[r][5] + bcol[5];
        o1.z = acc[r][6] + bcol[6]; o1.w = acc[r][7] + bcol[7];
        long ro = (long)(row0 + ty * 8 + r) * ldc + col0 + tx * 4;
        *(float4*)&C[ro]      = o0;
        *(float4*)&C[ro + 64] = o1;
    }
}

// ------------------------- region pooling (mean over 8x8) --------------------
__global__ void pool_kernel(const float* __restrict__ qkv,
                            float* __restrict__ qr, float* __restrict__ kr)
{
    int n = blockIdx.x, b = blockIdx.y, c = threadIdx.x;
    int h0 = (n / NWIN) * RS, w0 = (n % NWIN) * RS;
    float sq = 0.f, sk = 0.f;
#pragma unroll 8
    for (int p = 0; p < 64; p++) {
        long pix = (long)(b * HH + h0 + (p >> 3)) * WW + w0 + (p & 7);
        sq += qkv[pix * 768 + c];
        sk += qkv[pix * 768 + 256 + c];
    }
    qr[(b * NREG + n) * CC + c] = sq * 0.015625f;
    kr[(b * NREG + n) * CC + c] = sk * 0.015625f;
}

// ------------------------- region routing: a_r + top-4 -----------------------
__global__ void route_kernel(const float* __restrict__ qr,
                             const float* __restrict__ kr,
                             int* __restrict__ idxr)
{
    __shared__ float qrow[CC];
    __shared__ float ar[64];
    int i = blockIdx.x, b = blockIdx.y, tid = threadIdx.x;
    for (int c = tid; c < CC; c += 64) qrow[c] = qr[(b * NREG + i) * CC + c];
    if (tid >= NREG && tid < 64) ar[tid] = -CUDART_INF_F;
    __syncthreads();
    if (tid < NREG) {
        const float* krow = &kr[(b * NREG + tid) * CC];
        float acc = 0.f;
#pragma unroll 8
        for (int c = 0; c < CC; c++) acc += qrow[c] * krow[c];
        ar[tid] = acc;
    }
    __syncthreads();
    if (tid == 0) {
#pragma unroll
        for (int t = 0; t < TOPK; t++) {
            float best = -CUDART_INF_F; int bi = 0;
            for (int j = 0; j < NREG; j++)
                if (ar[j] > best) { best = ar[j]; bi = j; }
            ar[bi] = -CUDART_INF_F;
            idxr[(b * NREG + i) * TOPK + t] = bi;
        }
    }
}

// ------------------------- sparse attention per (region, head, batch) --------
// LePE (depthwise 3x3 on v + bias) fused into the epilogue.
// smem: q(64x32) + v(256x33) + scores(32x256)  = 74752 bytes  (K lives in regs)
#define ATTN_SMEM_FLOATS (64*32 + 256*33 + 32*256)
#define ATTN_SMEM_BYTES  (ATTN_SMEM_FLOATS * 4)

__global__ __launch_bounds__(256)
void attn_kernel(const float* __restrict__ qkv,
                 const int* __restrict__ idxr,
                 const float* __restrict__ lw,
                 const float* __restrict__ lb,
                 float* __restrict__ ao)
{
    const int n = blockIdx.x, m = blockIdx.y, b = blockIdx.z;
    extern __shared__ float sm[];
    float* q_s = sm;                      // 64*32
    float* v_s = sm + 64 * 32;            // 256*33
    float* sc  = v_s + 256 * 33;          // 32*256
    __shared__ int sidx[TOPK];

    const int tid = threadIdx.x;
    if (tid < TOPK) sidx[tid] = idxr[(b * NREG + n) * TOPK + tid];
    __syncthreads();

    const int h0 = (n / NWIN) * RS, w0 = (n % NWIN) * RS;
    const int lane = tid & 31, wrp = tid >> 5;
    const int ch = m * 32 + lane;         // this thread's output channel

    // per-thread lepe weights/bias for channel ch (fixed per thread)
    float lwr[9];
#pragma unroll
    for (int i = 0; i < 9; i++) lwr[i] = __ldg(&lw[ch * 9 + i]);
    const float lbr = __ldg(&lb[ch]);

    // load Q tile (scaled by C^-0.5 = 1/16)
#pragma unroll
    for (int i = 0; i < 8; i++) {
        int e = tid + i * 256;
        int s = e >> 5, d = e & 31;
        long pix = (long)(b * HH + h0 + (s >> 3)) * WW + w0 + (s & 7);
        q_s[e] = qkv[pix * 768 + m * 32 + d] * 0.0625f;
    }

    // load gathered K directly into registers; V into shared (one row per thread)
    float kreg[32];
    {
        int t  = tid;
        int r  = sidx[t >> 6];
        int sp = t & 63;
        int hi = (r / NWIN) * RS + (sp >> 3);
        int wi = (r % NWIN) * RS + (sp & 7);
        long base = (long)((b * HH + hi) * WW + wi) * 768;
        const float* kp = qkv + base + 256 + m * 32;
        const float* vp = qkv + base + 512 + m * 32;
#pragma unroll
        for (int d4 = 0; d4 < 8; d4++) {
            float4 kv = *(const float4*)(kp + d4 * 4);
            float4 vv = *(const float4*)(vp + d4 * 4);
            kreg[d4*4+0] = kv.x; kreg[d4*4+1] = kv.y;
            kreg[d4*4+2] = kv.z; kreg[d4*4+3] = kv.w;
            int o = t * 33 + d4 * 4;
            v_s[o]   = vv.x; v_s[o+1] = vv.y; v_s[o+2] = vv.z; v_s[o+3] = vv.w;
        }
    }
    __syncthreads();

    for (int ph = 0; ph < 2; ph++) {
        // ---- scores for rows [ph*32, ph*32+32), column = tid ----
        for (int s = 0; s < 32; s++) {
            const float4* q4 = (const float4*)&q_s[(ph * 32 + s) * 32];
            float acc = 0.f;
#pragma unroll
            for (int i = 0; i < 8; i++) {
                float4 qv = q4[i];
                acc += qv.x * kreg[i*4]   + qv.y * kreg[i*4+1]
                     + qv.z * kreg[i*4+2] + qv.w * kreg[i*4+3];
            }
            sc[s * 256 + tid] = acc;
        }
        __syncthreads();

        // ---- per-row exact top-32 + softmax + AV + fused lepe (warp per row) --
        for (int rr = 0; rr < 4; rr++) {
            int sl = wrp * 4 + rr;                  // phase-local row
            float f[8]; unsigned u[8];
#pragma unroll
            for (int i = 0; i < 8; i++) f[i] = sc[sl * 256 + lane + 32 * i];
#pragma unroll
            for (int i = 0; i < 8; i++) {
                unsigned t = __float_as_uint(f[i]);
                u[i] = (t & 0x80000000u) ? ~t : (t | 0x80000000u);
            }
            // MSB-first radix select: largest P with count(u >= P) >= 32
            unsigned P = 0;
            for (int bit = 31; bit >= 0; --bit) {
                unsigned cand = P | (1u << bit);
                int c8 = 0;
#pragma unroll
                for (int i = 0; i < 8; i++) c8 += (u[i] >= cand) ? 1 : 0;
                int cnt = __reduce_add_sync(FULLMASK, c8);
                if (cnt >= 32) { P = cand; if (cnt == 32) break; }
            }
            // threshold back to float (shift for exp; selected values >= Tf)
            float Tf = (P & 0x80000000u) ? __uint_as_float(P & 0x7fffffffu)
                                         : __uint_as_float(~P);
            float w[8]; float lsum = 0.f; unsigned selbits = 0;
#pragma unroll
            for (int i = 0; i < 8; i++) {
                bool sel = (u[i] >= P);
                w[i] = sel ? __expf(f[i] - Tf) : 0.f;
                lsum += w[i];
                selbits |= sel ? (1u << i) : 0u;
            }
#pragma unroll
            for (int o = 16; o; o >>= 1) lsum += __shfl_xor_sync(FULLMASK, lsum, o);
            float rcp = __frcp_rn(lsum);

            float acc = 0.f;
#pragma unroll
            for (int i = 0; i < 8; i++) {
                unsigned bal = __ballot_sync(FULLMASK, (selbits >> i) & 1);
                while (bal) {
                    int L = __ffs(bal) - 1; bal &= bal - 1;
                    float wk = __shfl_sync(FULLMASK, w[i], L);
                    acc += wk * v_s[(L + 32 * i) * 33 + lane];
                }
            }
            acc *= rcp;

            // ---- fused lepe: depthwise 3x3 on v at this pixel/channel ----
            int s  = ph * 32 + sl;
            int hi = h0 + (s >> 3), wi = w0 + (s & 7);
            float lp = lbr;
#pragma unroll
            for (int dy = 0; dy < 3; dy++) {
                int h2 = hi + dy - 1;
                if ((unsigned)h2 >= (unsigned)HH) continue;
#pragma unroll
                for (int dx = 0; dx < 3; dx++) {
                    int w2 = wi + dx - 1;
                    if ((unsigned)w2 >= (unsigned)WW) continue;
                    lp += qkv[(long)((b * HH + h2) * WW + w2) * 768 + 512 + ch]
                        * lwr[dy * 3 + dx];
                }
            }

            long pix = (long)(b * HH + hi) * WW + wi;
            ao[pix * 256 + ch] = acc + lp;
        }
        __syncthreads();
    }
}

// ------------------------- launch ---------------------------------------------
extern "C" void kernel_launch(void* const* d_in, const int* in_sizes, int n_in,
                              void* d_out, int out_size)
{
    const float* x      = (const float*)d_in[0];
    const float* qkv_w  = (const float*)d_in[1];
    const float* qkv_b  = (const float*)d_in[2];
    const float* lepe_w = (const float*)d_in[3];
    const float* lepe_b = (const float*)d_in[4];
    const float* out_w  = (const float*)d_in[5];
    const float* out_b  = (const float*)d_in[6];
    float* y = (float*)d_out;

    float *qkv_p, *ao_p, *qr_p, *kr_p; int* idx_p;
    cudaGetSymbolAddress((void**)&qkv_p, g_qkv);
    cudaGetSymbolAddress((void**)&ao_p,  g_ao);
    cudaGetSymbolAddress((void**)&qr_p,  g_qr);
    cudaGetSymbolAddress((void**)&kr_p,  g_kr);
    cudaGetSymbolAddress((void**)&idx_p, g_idx);

    cudaFuncSetAttribute(attn_kernel,
                         cudaFuncAttributeMaxDynamicSharedMemorySize,
                         ATTN_SMEM_BYTES);

    // 1) QKV projection: (25088x256) @ (768x256)^T + b -> g_qkv
    gemm_bias_kernel<<<dim3(768 / BN, NPIX / BM), 256>>>(
        x, CC, qkv_w, qkv_b, qkv_p, 768, CC);

    // 2) region pooling
    pool_kernel<<<dim3(NREG, BATCH), CC>>>(qkv_p, qr_p, kr_p);

    // 3) coarse routing top-4
    route_kernel<<<dim3(NREG, BATCH), 64>>>(qr_p, kr_p, idx_p);

    // 4) sparse attention with fused lepe
    attn_kernel<<<dim3(NREG, NH, BATCH), 256, ATTN_SMEM_BYTES>>>(
        qkv_p, idx_p, lepe_w, lepe_b, ao_p);

    // 5) output projection -> d_out
    gemm_bias_kernel<<<dim3(CC / BN, NPIX / BM), 256>>>(
        ao_p, CC, out_w, out_b, y, CC, CC);
}